// round 4
// baseline (speedup 1.0000x reference)
#include <cuda_runtime.h>
#include <math.h>
#include <stdint.h>

#define Bdim 8
#define Ndim 256
#define Ddim 128
#define K2   256

// Scratch for per-node projections (allocation-free rule -> device globals)
__device__ float g_Pi[Bdim * Ndim * K2];
__device__ float g_Pj[Bdim * Ndim * K2];

// ---------------------------------------------------------------------------
// Kernel 1 (proven): Pi = x@W1a + x_next@W1b + b1 ; Pj = x@W1c + x_next@W1d
// ---------------------------------------------------------------------------
__global__ void __launch_bounds__(256) proj_kernel(
    const float* __restrict__ x, const float* __restrict__ W1,
    const float* __restrict__ b1, float* __restrict__ outTour, int hasTour)
{
    __shared__ float xr[9][128];
    const int b  = blockIdx.x;
    const int n0 = blockIdx.y * 8;
    const int tid = threadIdx.x;

    for (int idx = tid; idx < 9 * 128; idx += 256) {
        int r = idx >> 7, c = idx & 127;
        int n = (n0 + r) & (Ndim - 1);
        xr[r][c] = x[((b * Ndim) + n) * Ddim + c];
    }
    __syncthreads();

    const int c = tid;
    float accPi[8], accPj[8];
#pragma unroll
    for (int r = 0; r < 8; r++) { accPi[r] = 0.f; accPj[r] = 0.f; }

    for (int k = 0; k < 128; k++) {
        float wa = W1[(k      ) * 256 + c];
        float wb = W1[(k + 128) * 256 + c];
        float wc = W1[(k + 256) * 256 + c];
        float wd = W1[(k + 384) * 256 + c];
#pragma unroll
        for (int r = 0; r < 8; r++) {
            float xi = xr[r][k];
            float xn = xr[r + 1][k];
            accPi[r] = fmaf(xi, wa, accPi[r]);
            accPi[r] = fmaf(xn, wb, accPi[r]);
            accPj[r] = fmaf(xi, wc, accPj[r]);
            accPj[r] = fmaf(xn, wd, accPj[r]);
        }
    }
    const float bias = b1[c];
#pragma unroll
    for (int r = 0; r < 8; r++) {
        int n = n0 + r;
        g_Pi[((b * Ndim) + n) * K2 + c] = accPi[r] + bias;
        g_Pj[((b * Ndim) + n) * K2 + c] = accPj[r];
    }
    if (hasTour && tid < 8) outTour[b * Ndim + n0 + tid] = (float)(n0 + tid);
}

// ---------------------------------------------------------------------------
// mma.sync m16n8k8 tf32 (verified layout in R3)
// ---------------------------------------------------------------------------
__device__ __forceinline__ void mma_tf32(float* d, const uint32_t* a,
                                         const uint32_t* b) {
    asm volatile(
        "mma.sync.aligned.m16n8k8.row.col.f32.tf32.tf32.f32 "
        "{%0,%1,%2,%3},{%4,%5,%6,%7},{%8,%9},{%0,%1,%2,%3};\n"
        : "+f"(d[0]), "+f"(d[1]), "+f"(d[2]), "+f"(d[3])
        : "r"(a[0]), "r"(a[1]), "r"(a[2]), "r"(a[3]), "r"(b[0]), "r"(b[1]));
}

// ---------------------------------------------------------------------------
// SMEM layout (floats)
// ---------------------------------------------------------------------------
#define PIS 260
#define OFF_W2F 0                        // packed B fragments: 32768 floats
#define OFF_PI  32768                    // 32 * 260 = 8320
#define OFF_PJ  (OFF_PI + 32 * PIS)      // 41088 ; 8 * 260 = 2080
#define OFF_B2  (OFF_PJ + 8 * PIS)       // 43168
#define OFF_W3  (OFF_B2 + 128)           // 43296
#define OFF_RED (OFF_W3 + 128)           // 43424 ; 512 floats
#define SMEM_FLOATS (OFF_RED + 512)      // 43936 -> 175744 bytes
#define SMEM_BYTES (SMEM_FLOATS * 4)

#define NTILES_PER_B 144                 // sum_{bi=0..7} (32 - 4*bi)
#define NTILES_TOT   (Bdim * NTILES_PER_B)   // 1152
#define GRID_PAIR    152
#define NTHREADS     512

// ---------------------------------------------------------------------------
// Kernel 2: persistent mma.sync tf32 pair kernel.
// CTA tile: M=256 pairs (32 i x 8 j), N=128 outs, K=256.
// 16 warps: wm = wid>>1 (M-split, 32 rows), wn = wid&1 (N-split, 64 cols).
// B fragments pre-packed per-thread so each k-step's 16 B floats are one
// contiguous 64B run -> 4 float4 LDS.
// ---------------------------------------------------------------------------
__global__ void __launch_bounds__(NTHREADS, 1) pair_mma_kernel(
    const float* __restrict__ W2g, const float* __restrict__ b2g,
    const float* __restrict__ W3g, const float* __restrict__ b3g,
    float* __restrict__ outM)
{
    extern __shared__ float sm[];
    float* sW2f = sm + OFF_W2F;
    float* sPi  = sm + OFF_PI;
    float* sPj  = sm + OFF_PJ;
    float* sB2  = sm + OFF_B2;
    float* sW3  = sm + OFF_W3;
    float* sRed = sm + OFF_RED;

    const int tid  = threadIdx.x;
    const int wid  = tid >> 5;
    const int lane = tid & 31;
    const int q = lane >> 2;     // fragment group id
    const int c = lane & 3;      // thread-in-group

    // --- pack B fragments: sW2f[((s*2+wn)*32+lane)*16 + a*2+e] = W2[8s+c+4e][64wn+8a+q]
    for (int idx = tid; idx < 32768; idx += NTHREADS) {
        int e   = idx & 1;
        int a   = (idx >> 1) & 7;
        int ln  = (idx >> 4) & 31;
        int wnn = (idx >> 9) & 1;
        int s   = idx >> 10;
        int k   = 8 * s + (ln & 3) + 4 * e;
        int n   = 64 * wnn + 8 * a + (ln >> 2);
        sW2f[idx] = W2g[k * 128 + n];
    }
    if (tid < 128) { sB2[tid] = b2g[tid]; sW3[tid] = W3g[tid]; }
    const float b3v = b3g[0];
    __syncthreads();

    const int wm = wid >> 1;          // 0..7 -> M base 32*wm
    const int wn = wid & 1;           // 0..1 -> N base 64*wn
    const int mb = wm * 32;
    const int nb = wn * 64;

    const float* piR0 = sPi + ((mb >> 3) + 0) * PIS;  // rows mb+q
    const float* piR1 = sPi + ((mb >> 3) + 1) * PIS;  // rows mb+q+8
    const float* piR2 = sPi + ((mb >> 3) + 2) * PIS;  // rows mb+q+16
    const float* piR3 = sPi + ((mb >> 3) + 3) * PIS;  // rows mb+q+24
    const float* pjR  = sPj + q * PIS;
    const float* myB  = sW2f + (wn * 32 + lane) * 16; // + s*1024 per k-step

    for (int t = blockIdx.x; t < NTILES_TOT; t += gridDim.x) {
        // map t -> (batch, bi, bj); tiles with bj >= 4*bi are (partially) valid
        int b = t / NTILES_PER_B;
        int r = t - b * NTILES_PER_B;
        int bi = 0;
        while (r >= 32 - 4 * bi) { r -= 32 - 4 * bi; bi++; }
        const int bj = 4 * bi + r;
        const int i0 = bi * 32, j0 = bj * 8;

        // stage Pi (32x256) / Pj (8x256) into padded smem
        {
            const float* gPi = g_Pi + (size_t)(b * Ndim + i0) * K2;
            const float* gPj = g_Pj + (size_t)(b * Ndim + j0) * K2;
            for (int idx = tid; idx < 32 * 64; idx += NTHREADS) {
                int row = idx >> 6, k4 = (idx & 63) << 2;
                *(float4*)(sPi + row * PIS + k4) = *(const float4*)(gPi + row * 256 + k4);
            }
            for (int idx = tid; idx < 8 * 64; idx += NTHREADS) {
                int row = idx >> 6, k4 = (idx & 63) << 2;
                *(float4*)(sPj + row * PIS + k4) = *(const float4*)(gPj + row * 256 + k4);
            }
        }
        __syncthreads();

        float acc[2][8][4];
#pragma unroll
        for (int am = 0; am < 2; am++)
#pragma unroll
            for (int a = 0; a < 8; a++)
#pragma unroll
                for (int e = 0; e < 4; e++) acc[am][a][e] = 0.f;

#pragma unroll 4
        for (int s = 0; s < 32; s++) {
            const int k1 = 8 * s + c, k2 = k1 + 4;

            // B fragments: 4 x float4, contiguous 64B per thread
            const float* bp = myB + s * 1024;
            float4 f0 = *(const float4*)(bp + 0);
            float4 f1 = *(const float4*)(bp + 4);
            float4 f2 = *(const float4*)(bp + 8);
            float4 f3 = *(const float4*)(bp + 12);
            uint32_t bf[8][2];
            bf[0][0] = __float_as_uint(f0.x); bf[0][1] = __float_as_uint(f0.y);
            bf[1][0] = __float_as_uint(f0.z); bf[1][1] = __float_as_uint(f0.w);
            bf[2][0] = __float_as_uint(f1.x); bf[2][1] = __float_as_uint(f1.y);
            bf[3][0] = __float_as_uint(f1.z); bf[3][1] = __float_as_uint(f1.w);
            bf[4][0] = __float_as_uint(f2.x); bf[4][1] = __float_as_uint(f2.y);
            bf[5][0] = __float_as_uint(f2.z); bf[5][1] = __float_as_uint(f2.w);
            bf[6][0] = __float_as_uint(f3.x); bf[6][1] = __float_as_uint(f3.y);
            bf[7][0] = __float_as_uint(f3.z); bf[7][1] = __float_as_uint(f3.w);

            const float pj1 = pjR[k1], pj2 = pjR[k2];

            {   // M-atom 0: rows mb+q, mb+q+8
                uint32_t af[4];
                af[0] = __float_as_uint(fmaxf(piR0[k1] + pj1, 0.f));
                af[1] = __float_as_uint(fmaxf(piR1[k1] + pj1, 0.f));
                af[2] = __float_as_uint(fmaxf(piR0[k2] + pj2, 0.f));
                af[3] = __float_as_uint(fmaxf(piR1[k2] + pj2, 0.f));
#pragma unroll
                for (int a = 0; a < 8; a++) mma_tf32(acc[0][a], af, bf[a]);
            }
            {   // M-atom 1: rows mb+q+16, mb+q+24
                uint32_t af[4];
                af[0] = __float_as_uint(fmaxf(piR2[k1] + pj1, 0.f));
                af[1] = __float_as_uint(fmaxf(piR3[k1] + pj1, 0.f));
                af[2] = __float_as_uint(fmaxf(piR2[k2] + pj2, 0.f));
                af[3] = __float_as_uint(fmaxf(piR3[k2] + pj2, 0.f));
#pragma unroll
                for (int a = 0; a < 8; a++) mma_tf32(acc[1][a], af, bf[a]);
            }
        }

        // epilogue: h = relu(acc + b2[n]); s = sum_n h*w3[n]; reduce lanes
#pragma unroll
        for (int am = 0; am < 2; am++) {
            float s0 = 0.f, s1 = 0.f;
#pragma unroll
            for (int a = 0; a < 8; a++) {
                int n0 = nb + 8 * a + 2 * c;
                float w0 = sW3[n0], w1 = sW3[n0 + 1];
                float bb0 = sB2[n0], bb1 = sB2[n0 + 1];
                s0 = fmaf(fmaxf(acc[am][a][0] + bb0, 0.f), w0, s0);
                s0 = fmaf(fmaxf(acc[am][a][1] + bb1, 0.f), w1, s0);
                s1 = fmaf(fmaxf(acc[am][a][2] + bb0, 0.f), w0, s1);
                s1 = fmaf(fmaxf(acc[am][a][3] + bb1, 0.f), w1, s1);
            }
            s0 += __shfl_xor_sync(0xffffffffu, s0, 1);
            s0 += __shfl_xor_sync(0xffffffffu, s0, 2);
            s1 += __shfl_xor_sync(0xffffffffu, s1, 1);
            s1 += __shfl_xor_sync(0xffffffffu, s1, 2);
            if (c == 0) {
                int m0 = mb + am * 16 + q;
                sRed[m0 * 2 + wn]       = s0;
                sRed[(m0 + 8) * 2 + wn] = s1;
            }
        }
        __syncthreads();

        if (tid < 256) {
            float s = sRed[tid * 2] + sRed[tid * 2 + 1];
            float val = tanhf(s + b3v);
            int i = i0 + (tid >> 3), j = j0 + (tid & 7);
            bool valid = (j >= i + 2) && ((j - i) != (Ndim - 1));
            outM[(b * Ndim + i) * Ndim + j] = valid ? val : 0.f;
        }
        // __syncthreads at next tile's staging guards sPi/sPj reuse; sRed reuse
        // is guarded because every warp wrote sRed after its k-loop finished.
    }
}

// ---------------------------------------------------------------------------
extern "C" void kernel_launch(void* const* d_in, const int* in_sizes, int n_in,
                              void* d_out, int out_size) {
    const float* x  = (const float*)d_in[0];
    const float* W1 = (const float*)d_in[1];
    const float* b1 = (const float*)d_in[2];
    const float* W2 = (const float*)d_in[3];
    const float* b2 = (const float*)d_in[4];
    const float* W3 = (const float*)d_in[5];
    const float* b3 = (const float*)d_in[6];

    float* out = (float*)d_out;
    const int matElems  = Bdim * Ndim * Ndim;
    const int tourElems = Bdim * Ndim;
    int hasTour = (out_size >= matElems + tourElems) ? 1 : 0;
    float* outTour = out;
    float* outM    = hasTour ? (out + tourElems) : out;

    // zero matrix region (covers fully-masked tiles); computed tiles overwrite
    cudaMemsetAsync(outM, 0, (size_t)matElems * sizeof(float), 0);

    dim3 g1(Bdim, Ndim / 8);
    proj_kernel<<<g1, 256>>>(x, W1, b1, outTour, hasTour);

    cudaFuncSetAttribute(pair_mma_kernel, cudaFuncAttributeMaxDynamicSharedMemorySize,
                         SMEM_BYTES);
    pair_mma_kernel<<<GRID_PAIR, NTHREADS, SMEM_BYTES>>>(W2, b2, W3, b3, outM);
}

// round 5
// speedup vs baseline: 1.6138x; 1.6138x over previous
#include <cuda_runtime.h>
#include <math.h>
#include <stdint.h>

#define Bdim 8
#define Ndim 256
#define Ddim 128
#define K2   256

// Scratch for per-node projections (allocation-free rule -> device globals)
__device__ float g_Pi[Bdim * Ndim * K2];
__device__ float g_Pj[Bdim * Ndim * K2];

// ---------------------------------------------------------------------------
// Kernel 1 (proven): Pi = x@W1a + x_next@W1b + b1 ; Pj = x@W1c + x_next@W1d
// ---------------------------------------------------------------------------
__global__ void __launch_bounds__(256) proj_kernel(
    const float* __restrict__ x, const float* __restrict__ W1,
    const float* __restrict__ b1, float* __restrict__ outTour, int hasTour)
{
    __shared__ float xr[9][128];
    const int b  = blockIdx.x;
    const int n0 = blockIdx.y * 8;
    const int tid = threadIdx.x;

    for (int idx = tid; idx < 9 * 128; idx += 256) {
        int r = idx >> 7, c = idx & 127;
        int n = (n0 + r) & (Ndim - 1);
        xr[r][c] = x[((b * Ndim) + n) * Ddim + c];
    }
    __syncthreads();

    const int c = tid;
    float accPi[8], accPj[8];
#pragma unroll
    for (int r = 0; r < 8; r++) { accPi[r] = 0.f; accPj[r] = 0.f; }

    for (int k = 0; k < 128; k++) {
        float wa = W1[(k      ) * 256 + c];
        float wb = W1[(k + 128) * 256 + c];
        float wc = W1[(k + 256) * 256 + c];
        float wd = W1[(k + 384) * 256 + c];
#pragma unroll
        for (int r = 0; r < 8; r++) {
            float xi = xr[r][k];
            float xn = xr[r + 1][k];
            accPi[r] = fmaf(xi, wa, accPi[r]);
            accPi[r] = fmaf(xn, wb, accPi[r]);
            accPj[r] = fmaf(xi, wc, accPj[r]);
            accPj[r] = fmaf(xn, wd, accPj[r]);
        }
    }
    const float bias = b1[c];
#pragma unroll
    for (int r = 0; r < 8; r++) {
        int n = n0 + r;
        g_Pi[((b * Ndim) + n) * K2 + c] = accPi[r] + bias;
        g_Pj[((b * Ndim) + n) * K2 + c] = accPj[r];
    }
    if (hasTour && tid < 8) outTour[b * Ndim + n0 + tid] = (float)(n0 + tid);
}

// ---------------------------------------------------------------------------
// mma.sync m16n8k8 tf32 (verified layout in R3)
// ---------------------------------------------------------------------------
__device__ __forceinline__ void mma_tf32(float* d, const uint32_t* a,
                                         const uint32_t* b) {
    asm volatile(
        "mma.sync.aligned.m16n8k8.row.col.f32.tf32.tf32.f32 "
        "{%0,%1,%2,%3},{%4,%5,%6,%7},{%8,%9},{%0,%1,%2,%3};\n"
        : "+f"(d[0]), "+f"(d[1]), "+f"(d[2]), "+f"(d[3])
        : "r"(a[0]), "r"(a[1]), "r"(a[2]), "r"(a[3]), "r"(b[0]), "r"(b[1]));
}

// ---------------------------------------------------------------------------
// SMEM layout (floats)
// ---------------------------------------------------------------------------
#define PIS 260
#define OFF_W2F 0                        // packed B fragments: 32768 floats
#define OFF_PI  32768                    // 32 * 260 = 8320
#define OFF_PJ  (OFF_PI + 32 * PIS)      // 41088 ; 8 * 260 = 2080
#define OFF_B2  (OFF_PJ + 8 * PIS)       // 43168
#define OFF_W3  (OFF_B2 + 128)           // 43296
#define OFF_RED (OFF_W3 + 128)           // 43424 ; 512 floats
#define SMEM_FLOATS (OFF_RED + 512)      // 43936 -> 175744 bytes
#define SMEM_BYTES (SMEM_FLOATS * 4)

#define NTILES_PER_B 144                 // sum_{bi=0..7} (32 - 4*bi)
#define NTILES_TOT   (Bdim * NTILES_PER_B)   // 1152
#define GRID_PAIR    152
#define NTHREADS     512

// ---------------------------------------------------------------------------
// Kernel 2: persistent mma.sync tf32 pair kernel.
// CTA tile: M=256 pairs (32 i x 8 j), N=128 outs, K=256.
// 16 warps: wm = wid>>1 (M-split, 32 rows), wn = wid&1 (N-split, 64 cols).
// B fragments packed as float4[((s*4+g)*2+wn)*32 + lane]:
//   lane stride 16B, contiguous 512B per warp-load -> conflict-free LDS.128.
//   float4 = { W2[k1][n0], W2[k2][n0], W2[k1][n1], W2[k2][n1] },
//   k1=8s+c, k2=8s+c+4, n0=64wn+16g+q... (a=2g), n1=64wn+8(2g+1)+q.
// ---------------------------------------------------------------------------
__global__ void __launch_bounds__(NTHREADS, 1) pair_mma_kernel(
    const float* __restrict__ W2g, const float* __restrict__ b2g,
    const float* __restrict__ W3g, const float* __restrict__ b3g,
    float* __restrict__ outM)
{
    extern __shared__ float sm[];
    float4* sW2f4 = (float4*)(sm + OFF_W2F);
    float* sPi  = sm + OFF_PI;
    float* sPj  = sm + OFF_PJ;
    float* sB2  = sm + OFF_B2;
    float* sW3  = sm + OFF_W3;
    float* sRed = sm + OFF_RED;

    const int tid  = threadIdx.x;
    const int wid  = tid >> 5;
    const int lane = tid & 31;
    const int q = lane >> 2;     // fragment group id
    const int c = lane & 3;      // thread-in-group

    // --- pack B fragments (one-time, 8192 float4s) ---
    // float4 index: ((s*4+g)*2 + wn)*32 + lane
    for (int idx = tid; idx < 8192; idx += NTHREADS) {
        int ln  = idx & 31;
        int wnn = (idx >> 5) & 1;
        int g   = (idx >> 6) & 3;
        int s   = idx >> 8;
        int cc  = ln & 3, qq = ln >> 2;
        int k1  = 8 * s + cc, k2 = k1 + 4;
        int n0  = 64 * wnn + 8 * (2 * g) + qq;
        int n1  = n0 + 8;
        float4 v;
        v.x = W2g[k1 * 128 + n0];
        v.y = W2g[k2 * 128 + n0];
        v.z = W2g[k1 * 128 + n1];
        v.w = W2g[k2 * 128 + n1];
        sW2f4[idx] = v;
    }
    if (tid < 128) { sB2[tid] = b2g[tid]; sW3[tid] = W3g[tid]; }
    const float b3v = b3g[0];
    __syncthreads();

    const int wm = wid >> 1;          // 0..7 -> M base 32*wm
    const int wn = wid & 1;           // 0..1 -> N base 64*wn
    const int mb = wm * 32;
    const int nb = wn * 64;

    const float* piR0 = sPi + ((mb >> 3) + 0) * PIS;  // rows mb+q
    const float* piR1 = sPi + ((mb >> 3) + 1) * PIS;  // rows mb+q+8
    const float* piR2 = sPi + ((mb >> 3) + 2) * PIS;  // rows mb+q+16
    const float* piR3 = sPi + ((mb >> 3) + 3) * PIS;  // rows mb+q+24
    const float* pjR  = sPj + q * PIS;
    const float4* myB = sW2f4 + wn * 32 + lane;       // + (s*4+g)*64

    for (int t = blockIdx.x; t < NTILES_TOT; t += gridDim.x) {
        // map t -> (batch, bi, bj); tiles with bj >= 4*bi are (partially) valid
        int b = t / NTILES_PER_B;
        int r = t - b * NTILES_PER_B;
        int bi = 0;
        while (r >= 32 - 4 * bi) { r -= 32 - 4 * bi; bi++; }
        const int bj = 4 * bi + r;
        const int i0 = bi * 32, j0 = bj * 8;

        // stage Pi (32x256) / Pj (8x256) into padded smem
        {
            const float* gPi = g_Pi + (size_t)(b * Ndim + i0) * K2;
            const float* gPj = g_Pj + (size_t)(b * Ndim + j0) * K2;
            for (int idx = tid; idx < 32 * 64; idx += NTHREADS) {
                int row = idx >> 6, k4 = (idx & 63) << 2;
                *(float4*)(sPi + row * PIS + k4) = *(const float4*)(gPi + row * 256 + k4);
            }
            for (int idx = tid; idx < 8 * 64; idx += NTHREADS) {
                int row = idx >> 6, k4 = (idx & 63) << 2;
                *(float4*)(sPj + row * PIS + k4) = *(const float4*)(gPj + row * 256 + k4);
            }
        }
        __syncthreads();

        float acc[2][8][4];
#pragma unroll
        for (int am = 0; am < 2; am++)
#pragma unroll
            for (int a = 0; a < 8; a++)
#pragma unroll
                for (int e = 0; e < 4; e++) acc[am][a][e] = 0.f;

#pragma unroll 4
        for (int s = 0; s < 32; s++) {
            const int k1 = 8 * s + c, k2 = k1 + 4;

            // B fragments: 4 conflict-free LDS.128
            float4 f0 = myB[(s * 4 + 0) * 64];
            float4 f1 = myB[(s * 4 + 1) * 64];
            float4 f2 = myB[(s * 4 + 2) * 64];
            float4 f3 = myB[(s * 4 + 3) * 64];
            uint32_t bf[8][2];
            bf[0][0] = __float_as_uint(f0.x); bf[0][1] = __float_as_uint(f0.y);
            bf[1][0] = __float_as_uint(f0.z); bf[1][1] = __float_as_uint(f0.w);
            bf[2][0] = __float_as_uint(f1.x); bf[2][1] = __float_as_uint(f1.y);
            bf[3][0] = __float_as_uint(f1.z); bf[3][1] = __float_as_uint(f1.w);
            bf[4][0] = __float_as_uint(f2.x); bf[4][1] = __float_as_uint(f2.y);
            bf[5][0] = __float_as_uint(f2.z); bf[5][1] = __float_as_uint(f2.w);
            bf[6][0] = __float_as_uint(f3.x); bf[6][1] = __float_as_uint(f3.y);
            bf[7][0] = __float_as_uint(f3.z); bf[7][1] = __float_as_uint(f3.w);

            const float pj1 = pjR[k1], pj2 = pjR[k2];

            {   // M-atom 0: rows mb+q, mb+q+8
                uint32_t af[4];
                af[0] = __float_as_uint(fmaxf(piR0[k1] + pj1, 0.f));
                af[1] = __float_as_uint(fmaxf(piR1[k1] + pj1, 0.f));
                af[2] = __float_as_uint(fmaxf(piR0[k2] + pj2, 0.f));
                af[3] = __float_as_uint(fmaxf(piR1[k2] + pj2, 0.f));
#pragma unroll
                for (int a = 0; a < 8; a++) mma_tf32(acc[0][a], af, bf[a]);
            }
            {   // M-atom 1: rows mb+q+16, mb+q+24
                uint32_t af[4];
                af[0] = __float_as_uint(fmaxf(piR2[k1] + pj1, 0.f));
                af[1] = __float_as_uint(fmaxf(piR3[k1] + pj1, 0.f));
                af[2] = __float_as_uint(fmaxf(piR2[k2] + pj2, 0.f));
                af[3] = __float_as_uint(fmaxf(piR3[k2] + pj2, 0.f));
#pragma unroll
                for (int a = 0; a < 8; a++) mma_tf32(acc[1][a], af, bf[a]);
            }
        }

        // epilogue: h = relu(acc + b2[n]); s = sum_n h*w3[n]; reduce lanes
#pragma unroll
        for (int am = 0; am < 2; am++) {
            float s0 = 0.f, s1 = 0.f;
#pragma unroll
            for (int a = 0; a < 8; a++) {
                int n0 = nb + 8 * a + 2 * c;
                float w0 = sW3[n0], w1 = sW3[n0 + 1];
                float bb0 = sB2[n0], bb1 = sB2[n0 + 1];
                s0 = fmaf(fmaxf(acc[am][a][0] + bb0, 0.f), w0, s0);
                s0 = fmaf(fmaxf(acc[am][a][1] + bb1, 0.f), w1, s0);
                s1 = fmaf(fmaxf(acc[am][a][2] + bb0, 0.f), w0, s1);
                s1 = fmaf(fmaxf(acc[am][a][3] + bb1, 0.f), w1, s1);
            }
            s0 += __shfl_xor_sync(0xffffffffu, s0, 1);
            s0 += __shfl_xor_sync(0xffffffffu, s0, 2);
            s1 += __shfl_xor_sync(0xffffffffu, s1, 1);
            s1 += __shfl_xor_sync(0xffffffffu, s1, 2);
            if (c == 0) {
                int m0 = mb + am * 16 + q;
                sRed[m0 * 2 + wn]       = s0;
                sRed[(m0 + 8) * 2 + wn] = s1;
            }
        }
        __syncthreads();

        if (tid < 256) {
            float s = sRed[tid * 2] + sRed[tid * 2 + 1];
            float val = tanhf(s + b3v);
            int i = i0 + (tid >> 3), j = j0 + (tid & 7);
            bool valid = (j >= i + 2) && ((j - i) != (Ndim - 1));
            outM[(b * Ndim + i) * Ndim + j] = valid ? val : 0.f;
        }
        // next-tile staging __syncthreads guards sPi/sPj/sRed reuse
    }
}

// ---------------------------------------------------------------------------
extern "C" void kernel_launch(void* const* d_in, const int* in_sizes, int n_in,
                              void* d_out, int out_size) {
    const float* x  = (const float*)d_in[0];
    const float* W1 = (const float*)d_in[1];
    const float* b1 = (const float*)d_in[2];
    const float* W2 = (const float*)d_in[3];
    const float* b2 = (const float*)d_in[4];
    const float* W3 = (const float*)d_in[5];
    const float* b3 = (const float*)d_in[6];

    float* out = (float*)d_out;
    const int matElems  = Bdim * Ndim * Ndim;
    const int tourElems = Bdim * Ndim;
    int hasTour = (out_size >= matElems + tourElems) ? 1 : 0;
    float* outTour = out;
    float* outM    = hasTour ? (out + tourElems) : out;

    // zero matrix region (covers fully-masked tiles); computed tiles overwrite
    cudaMemsetAsync(outM, 0, (size_t)matElems * sizeof(float), 0);

    dim3 g1(Bdim, Ndim / 8);
    proj_kernel<<<g1, 256>>>(x, W1, b1, outTour, hasTour);

    cudaFuncSetAttribute(pair_mma_kernel, cudaFuncAttributeMaxDynamicSharedMemorySize,
                         SMEM_BYTES);
    pair_mma_kernel<<<GRID_PAIR, NTHREADS, SMEM_BYTES>>>(W2, b2, W3, b3, outM);
}